// round 15
// baseline (speedup 1.0000x reference)
#include <cuda_runtime.h>
#include <cuda_bf16.h>
#include <math.h>
#include <stdint.h>

// Problem constants
#define BB 64
#define SS 512
#define DD 1024
#define HH 1024
#define G4H 4096          // 4*H
#define KW 2048           // D+H
#define KP 3072           // split-bf16 packed K for x-GEMM (hi|hi|lo)
#define KHP2 2048         // packed h cols: [hi | lo]
#define OUT_MAIN 33554432 // B*S*H
#define RNBLK 128
#define RNTHR 256

// tcgen05 availability: only in the arch-specific (sm_103a/sm_100a) compile pass.
#if defined(__CUDA_ARCH_FEAT_SM103_ALL) || defined(__CUDA_ARCH_FEAT_SM100_ALL) || \
    (defined(__CUDA_ARCH_SPECIFIC__) && (__CUDA_ARCH_SPECIFIC__ >= 1000))
#define HAS_TC5 1
#else
#define HAS_TC5 0
#endif

// ---------------- device scratch (no allocs allowed) ----------------
__device__ float g_gx[(size_t)SS * BB * G4H];            // [s][b][4H]
__device__ __align__(1024) __nv_bfloat16 g_a[(size_t)(BB * SS) * KP];
__device__ __align__(1024) __nv_bfloat16 g_b[(size_t)G4H * KP];
__device__ __nv_bfloat16 g_bh[(size_t)RNBLK * 32 * KHP2];// Wh' [128*32][2048] = [Whi|Wlo]
__device__ __align__(1024) __nv_bfloat16 g_hA[2][131072];// 2 x 256KB stage images
__device__ __nv_bfloat16 g_hsp[2][(size_t)BB * KHP2];    // SIMT-fallback h buffers
__device__ float g_hfin[BB * HH];
__device__ float g_cfin[BB * HH];
__device__ unsigned g_arrive;                            // SIMT-fallback barrier
__device__ unsigned g_epoch;                             // SIMT-fallback barrier
__device__ unsigned g_cready[16];                        // per-chunk producer counters

// ---------------- PTX helpers ----------------
__device__ __forceinline__ uint32_t smem_u32(const void* p) {
    uint32_t a;
    asm("{ .reg .u64 t; cvta.to.shared.u64 t, %1; cvt.u32.u64 %0, t; }" : "=r"(a) : "l"(p));
    return a;
}

#if HAS_TC5
__device__ __forceinline__ uint32_t elect1() {
    uint32_t p;
    asm volatile("{\n\t.reg .pred p;\n\telect.sync _|p, 0xFFFFFFFF;\n\tselp.b32 %0, 1, 0, p;\n\t}" : "=r"(p));
    return p;
}
__device__ __forceinline__ void mbar_init(uint32_t mbar, uint32_t cnt) {
    asm volatile("mbarrier.init.shared.b64 [%0], %1;" :: "r"(mbar), "r"(cnt) : "memory");
}
__device__ __forceinline__ void mbar_expect_tx(uint32_t mbar, uint32_t bytes) {
    asm volatile("mbarrier.arrive.expect_tx.shared.b64 _, [%0], %1;"
                 :: "r"(mbar), "r"(bytes) : "memory");
}
__device__ __forceinline__ void bulk_g2s(uint32_t dst, const void* src, uint32_t bytes,
                                         uint32_t mbar) {
    asm volatile(
        "cp.async.bulk.shared::cta.global.mbarrier::complete_tx::bytes [%0], [%1], %2, [%3];"
        :: "r"(dst), "l"(src), "r"(bytes), "r"(mbar) : "memory");
}
__device__ __forceinline__ void mbar_wait(uint32_t mbar, uint32_t parity) {
    asm volatile(
        "{\n\t.reg .pred P1;\n\t"
        "WL%=:\n\t"
        "mbarrier.try_wait.parity.acquire.cta.shared::cta.b64 P1, [%0], %1, 0x989680;\n\t"
        "@P1 bra.uni WD%=;\n\t"
        "bra.uni WL%=;\n\t"
        "WD%=:\n\t}"
        :: "r"(mbar), "r"(parity) : "memory");
}
__device__ __forceinline__ void mma_f16_ss(uint32_t d, uint64_t ad, uint64_t bd,
                                           uint32_t idesc, uint32_t en) {
    asm volatile(
        "{\n\t.reg .pred p;\n\tsetp.ne.u32 p, %5, 0;\n\t"
        "tcgen05.mma.cta_group::1.kind::f16 [%0], %1, %2, %3, {%4, %4, %4, %4}, p;\n\t}"
        :: "r"(d), "l"(ad), "l"(bd), "r"(idesc), "r"(0u), "r"(en) : "memory");
}
__device__ __forceinline__ void tc_commit(uint32_t mbar) {
    asm volatile("tcgen05.commit.cta_group::1.mbarrier::arrive::one.shared::cluster.b64 [%0];"
                 :: "r"(mbar) : "memory");
}
#define LDTM_X32(r, addr) \
    asm volatile( \
        "tcgen05.ld.sync.aligned.32x32b.x32.b32 " \
        "{%0, %1, %2, %3, %4, %5, %6, %7, %8, %9, %10, %11, %12, %13, %14, %15, " \
        " %16, %17, %18, %19, %20, %21, %22, %23, %24, %25, %26, %27, %28, %29, %30, %31}, [%32];" \
        : "=r"((r)[0]), "=r"((r)[1]), "=r"((r)[2]), "=r"((r)[3]), \
          "=r"((r)[4]), "=r"((r)[5]), "=r"((r)[6]), "=r"((r)[7]), \
          "=r"((r)[8]), "=r"((r)[9]), "=r"((r)[10]), "=r"((r)[11]), \
          "=r"((r)[12]), "=r"((r)[13]), "=r"((r)[14]), "=r"((r)[15]), \
          "=r"((r)[16]), "=r"((r)[17]), "=r"((r)[18]), "=r"((r)[19]), \
          "=r"((r)[20]), "=r"((r)[21]), "=r"((r)[22]), "=r"((r)[23]), \
          "=r"((r)[24]), "=r"((r)[25]), "=r"((r)[26]), "=r"((r)[27]), \
          "=r"((r)[28]), "=r"((r)[29]), "=r"((r)[30]), "=r"((r)[31]) \
        : "r"(addr))
#endif  // HAS_TC5

static constexpr uint64_t DESC_BASE_SW128 =
    (2ULL << 61) | (1ULL << 46) | (64ULL << 32) | (1ULL << 16);
#define MK_DESC(a) (DESC_BASE_SW128 | (((uint64_t)((a) >> 4)) & 0x3FFF))
#define SWZ(o) ((o) ^ (((o) >> 3) & 0x70))

// idesc: kind::f16, dtype=F32, a/b=BF16
#define GEMM_IDESC ((1u << 4) | (1u << 7) | (1u << 10) | ((256u / 8u) << 17) | ((128u / 16u) << 24))
// M=128, N=32 — identical to the validated test_mma.cu config (0x8080490)
#define REC_IDESC  ((1u << 4) | (1u << 7) | (1u << 10) | ((32u / 8u) << 17) | ((128u / 16u) << 24))

// ---------------- init: zero h0 images + chunk counters ----------------
__global__ void init_kernel() {
    int i = blockIdx.x * blockDim.x + threadIdx.x;
    if (i < 65536) ((uint32_t*)g_hA[0])[i] = 0u;
    if (i < (BB * KHP2) / 2) ((uint32_t*)g_hsp[0])[i] = 0u;
    if (i < 16) g_cready[i] = 0u;
}

// ---------------- split-bf16 conversion ----------------
__device__ __forceinline__ void split4(float4 v, uint2& hq, uint2& lq) {
    __nv_bfloat16 h0 = __float2bfloat16(v.x), h1 = __float2bfloat16(v.y);
    __nv_bfloat16 h2 = __float2bfloat16(v.z), h3 = __float2bfloat16(v.w);
    __nv_bfloat16 l0 = __float2bfloat16(v.x - __bfloat162float(h0));
    __nv_bfloat16 l1 = __float2bfloat16(v.y - __bfloat162float(h1));
    __nv_bfloat16 l2 = __float2bfloat16(v.z - __bfloat162float(h2));
    __nv_bfloat16 l3 = __float2bfloat16(v.w - __bfloat162float(h3));
    hq.x = (uint32_t)__bfloat16_as_ushort(h0) | ((uint32_t)__bfloat16_as_ushort(h1) << 16);
    hq.y = (uint32_t)__bfloat16_as_ushort(h2) | ((uint32_t)__bfloat16_as_ushort(h3) << 16);
    lq.x = (uint32_t)__bfloat16_as_ushort(l0) | ((uint32_t)__bfloat16_as_ushort(l1) << 16);
    lq.y = (uint32_t)__bfloat16_as_ushort(l2) | ((uint32_t)__bfloat16_as_ushort(l3) << 16);
}

// tiled destination byte offset inside g_a: tile row r (0..127), packed col kp
__device__ __forceinline__ size_t a_off(int bm, int r, int kp) {
    int s = kp >> 6, c = kp & 63;
    return ((size_t)(bm * 48 + s) << 14) + SWZ((uint32_t)(r * 128 + c * 2));
}
// tiled destination byte offset inside g_b: tile row r (0..255), packed col kp
__device__ __forceinline__ size_t b_off(int bn, int r, int kp) {
    int s = kp >> 6, c = kp & 63;
    return ((size_t)(bn * 48 + s) << 15) + SWZ((uint32_t)(r * 128 + c * 2));
}

// A' = [hi | hi | lo] from x [32768][1024] -> tiled swizzled g_a
__global__ __launch_bounds__(256) void conv_a_kernel(const float* __restrict__ x) {
    int gid = blockIdx.x * 256 + threadIdx.x;
    int m = gid >> 8;
    int kq = (gid & 255) << 2;
    float4 v = *(const float4*)(x + (size_t)m * DD + kq);
    uint2 hq, lq;
    split4(v, hq, lq);
    int bm = m >> 7, r = m & 127;
    char* base = (char*)g_a;
    *(uint2*)(base + a_off(bm, r, kq)) = hq;
    *(uint2*)(base + a_off(bm, r, 1024 + kq)) = hq;
    *(uint2*)(base + a_off(bm, r, 2048 + kq)) = lq;
}

// B' = [hi | lo | hi] from W rows [4096][2048] (x-part cols) -> tiled swizzled g_b
__global__ __launch_bounds__(256) void conv_b_kernel(const float* __restrict__ W) {
    int gid = blockIdx.x * 256 + threadIdx.x;
    int n = gid >> 8;
    int kq = (gid & 255) << 2;
    float4 v = *(const float4*)(W + (size_t)n * KW + kq);
    uint2 hq, lq;
    split4(v, hq, lq);
    int bn = n >> 8, r = n & 255;
    char* base = (char*)g_b;
    *(uint2*)(base + b_off(bn, r, kq)) = hq;
    *(uint2*)(base + b_off(bn, r, 1024 + kq)) = lq;
    *(uint2*)(base + b_off(bn, r, 2048 + kq)) = hq;
}

// Wh' packed per recurrent CTA: row rp = cta*32 + gate*8 + u, [Whi | Wlo] (2048),
// source W rows n = gate*1024 + cta*8 + u, h-part cols 1024..2047.
__global__ __launch_bounds__(256) void conv_bh_kernel(const float* __restrict__ W) {
    int gid = blockIdx.x * 256 + threadIdx.x;
    int n = gid >> 8;
    int kq = (gid & 255) << 2;
    float4 v = *(const float4*)(W + (size_t)n * KW + DD + kq);
    uint2 hq, lq;
    split4(v, hq, lq);
    int gate = n >> 10, j = n & 1023;
    int rp = (j >> 3) * 32 + gate * 8 + (j & 7);
    char* base = (char*)(g_bh + (size_t)rp * KHP2 + kq);
    *(uint2*)(base) = hq;
    *(uint2*)(base + 1024 * 2) = lq;
}

// ---------------- tcgen05 x-GEMM (unchanged from R8) --------
#define GSTG 49152
#define GEMM_SMEM (1024 + 4 * GSTG)  // 197632
__global__ __launch_bounds__(128, 1) void gemm_tc(const float* __restrict__ bias) {
#if HAS_TC5
    extern __shared__ __align__(1024) char smem[];
    uint32_t sbase = smem_u32(smem);
    int tid = threadIdx.x;
    int wid = tid >> 5, lane = tid & 31;
    int bn = blockIdx.x;  // 0..15
    int bm = blockIdx.y;  // 0..255

    if (wid == 0) {
        asm volatile("tcgen05.alloc.cta_group::1.sync.aligned.shared::cta.b32 [%0], %1;"
                     :: "r"(sbase), "r"(256) : "memory");
        asm volatile("tcgen05.relinquish_alloc_permit.cta_group::1.sync.aligned;");
    }
    if (tid == 0) {
#pragma unroll
        for (int i = 0; i < 4; i++) {
            mbar_init(sbase + 8 + i * 8, 1);
            mbar_init(sbase + 40 + i * 8, 1);
        }
        mbar_init(sbase + 72, 1);
    }
    __syncthreads();
    uint32_t tmem;
    asm volatile("ld.shared.b32 %0, [%1];" : "=r"(tmem) : "r"(sbase));

    const char* Asrc = (const char*)g_a + ((size_t)bm * 48 << 14);
    const char* Bsrc = (const char*)g_b + ((size_t)bn * 48 << 15);

    if (tid == 0) {
#pragma unroll
        for (int s = 0; s < 4; s++) {
            uint32_t full = sbase + 8 + s * 8;
            uint32_t dst = sbase + 1024 + s * GSTG;
            mbar_expect_tx(full, GSTG);
            bulk_g2s(dst, Asrc + (size_t)s * 16384, 16384, full);
            bulk_g2s(dst + 16384, Bsrc + (size_t)s * 32768, 32768, full);
        }
        for (int s = 0; s < 48; s++) {
            int b = s & 3;
            uint32_t p = (s >> 2) & 1;
            mbar_wait(sbase + 8 + b * 8, p);
            uint64_t ad = MK_DESC(sbase + 1024 + b * GSTG);
            uint64_t bd = MK_DESC(sbase + 1024 + b * GSTG + 16384);
#pragma unroll
            for (int k = 0; k < 4; k++)
                mma_f16_ss(tmem, ad + k * 2, bd + k * 2, GEMM_IDESC,
                           (s > 0 || k > 0) ? 1u : 0u);
            tc_commit(sbase + 40 + b * 8);
            if (s + 4 < 48) {
                mbar_wait(sbase + 40 + b * 8, p);  // MMA on buffer b done
                int sn = s + 4;
                uint32_t full = sbase + 8 + b * 8;
                uint32_t dst = sbase + 1024 + b * GSTG;
                mbar_expect_tx(full, GSTG);
                bulk_g2s(dst, Asrc + (size_t)sn * 16384, 16384, full);
                bulk_g2s(dst + 16384, Bsrc + (size_t)sn * 32768, 32768, full);
            }
        }
        tc_commit(sbase + 72);  // tracks all issued MMAs
    }
    mbar_wait(sbase + 72, 0);
    asm volatile("tcgen05.fence::after_thread_sync;" ::: "memory");

    {
        int m = bm * 128 + wid * 32 + lane;
        int s_ = m & 511, b_ = m >> 9;
        float* orow = g_gx + (size_t)(s_ * BB + b_) * G4H + bn * 256;
        const float* brow = bias + bn * 256;
#pragma unroll 1
        for (int cb = 0; cb < 256; cb += 32) {
            uint32_t r[32];
            LDTM_X32(r, tmem + cb);
            asm volatile("tcgen05.wait::ld.sync.aligned;" ::: "memory");
#pragma unroll
            for (int j = 0; j < 32; j += 4) {
                float4 v;
                v.x = __uint_as_float(r[j + 0]) + __ldg(brow + cb + j + 0);
                v.y = __uint_as_float(r[j + 1]) + __ldg(brow + cb + j + 1);
                v.z = __uint_as_float(r[j + 2]) + __ldg(brow + cb + j + 2);
                v.w = __uint_as_float(r[j + 3]) + __ldg(brow + cb + j + 3);
                *(float4*)(orow + cb + j) = v;
            }
        }
    }
    __syncthreads();
    if (wid == 0) {
        asm volatile("tcgen05.dealloc.cta_group::1.sync.aligned.b32 %0, %1;"
                     :: "r"(tmem), "r"(256));
    }
#else
    // SIMT fallback for the non-arch-specific PTX pass (never selected on GB300).
    int tid = threadIdx.x;
    int bn = blockIdx.x, bm = blockIdx.y;
    const char* ab = (const char*)g_a;
    const char* bb = (const char*)g_b;
    for (int idx = tid; idx < 128 * 256; idx += 128) {
        int mi = idx >> 8, ni = idx & 255;
        float acc = 0.f;
        for (int kp = 0; kp < KP; kp++) {
            __nv_bfloat16 av = *(const __nv_bfloat16*)(ab + a_off(bm, mi, kp));
            __nv_bfloat16 bv = *(const __nv_bfloat16*)(bb + b_off(bn, ni, kp));
            acc += __bfloat162float(av) * __bfloat162float(bv);
        }
        int m = bm * 128 + mi, n = bn * 256 + ni;
        int s_ = m & 511, b_ = m >> 9;
        g_gx[(size_t)(s_ * BB + b_) * G4H + n] = acc + bias[n];
    }
#endif
}

// ---------------- grid barrier (SIMT fallback only) ----------------
__device__ __forceinline__ void grid_bar() {
    __syncthreads();
    if (threadIdx.x == 0) {
        __threadfence();
        unsigned e = g_epoch;
        unsigned old = atomicAdd(&g_arrive, 1);
        if (old == RNBLK - 1) {
            g_arrive = 0;
            __threadfence();
            atomicExch(&g_epoch, e + 1);
        } else {
            while (*(volatile unsigned*)&g_epoch == e) {}
            __threadfence();
        }
    }
    __syncthreads();
}

// ---------------- persistent tcgen05 recurrent kernel ----------------
// Global barrier replaced by per-chunk dataflow sync: chunk c of the h image
// is produced by CTAs 8c..8c+7; g_cready[c] counts producer signals. The
// control thread polls readiness right before each chunk's TMA issue, so
// consumption overlaps straggling producers. Double-buffered image remains
// safe (skew self-limited to <1 step; see proof in commit message).
#define RW_OFF 1024
#define RA_OFF (RW_OFF + 131072)    // 132096, 4 x 16384
#define RGX_OFF (RA_OFF + 65536)    // 197632
#define RLO_OFF (RGX_OFF + 8192)    // 205824
#define RSMEM (RLO_OFF + 8448)      // 214272
__global__ __launch_bounds__(RNTHR, 1) void lstm_tc(float* __restrict__ outp) {
#if HAS_TC5
    extern __shared__ __align__(1024) char smem[];
    uint32_t sbase = smem_u32(smem);
    int tid = threadIdx.x, wid = tid >> 5, lane = tid & 31;
    int cta = blockIdx.x;
    int jb = cta * 8;

    if (wid == 0) {
        asm volatile("tcgen05.alloc.cta_group::1.sync.aligned.shared::cta.b32 [%0], %1;"
                     :: "r"(sbase), "r"(32) : "memory");
        asm volatile("tcgen05.relinquish_alloc_permit.cta_group::1.sync.aligned;");
    }
    // mbarriers: tma_full[4] at +8..+32, done[4] at +40..+64, step_done at +72
    if (tid == 0) {
#pragma unroll
        for (int i = 0; i < 4; i++) {
            mbar_init(sbase + 8 + i * 8, 1);
            mbar_init(sbase + 40 + i * 8, 1);
        }
        mbar_init(sbase + 72, 1);
    }
    __syncthreads();
    uint32_t tmem;
    asm volatile("ld.shared.b32 %0, [%1];" : "=r"(tmem) : "r"(sbase));

    // Load resident Wh' slice: 32 chunks x (32 rows x 128B), SW128 swizzled.
    {
        const __nv_bfloat16* wsrc = g_bh + (size_t)cta * 32 * KHP2;
        for (int i = tid; i < 8192; i += RNTHR) {
            int lc = i >> 8, q = i & 255;
            uint4 v = *(const uint4*)(wsrc + (size_t)lc * KHP2 + q * 8);
            int c = q >> 3;
            uint32_t off = (uint32_t)lc * 128 + (q & 7) * 16;
            *(uint4*)(smem + RW_OFF + c * 4096 + SWZ(off)) = v;
        }
    }
    __syncthreads();

    float* gxs = (float*)(smem + RGX_OFF);
    float* loD = (float*)(smem + RLO_OFF);
    float creg[8];
#pragma unroll
    for (int u = 0; u < 8; u++) creg[u] = 0.f;
    int m_ep = wid * 32 + lane;

    int wchunk = jb >> 6;
    uint32_t wc_hi = SWZ((uint32_t)(jb & 63) * 2);

    for (int t = 0; t < SS; t++) {
        // stage Gx(t) into smem (ordered vs epilogue by the epilogue syncthreads)
        {
            int b2 = tid >> 2, gate = tid & 3;
            const float* src = g_gx + (size_t)t * BB * G4H + (size_t)b2 * G4H +
                               gate * HH + jb;
            float4 v0 = *(const float4*)src;
            float4 v1 = *(const float4*)(src + 4);
            float* dst = gxs + b2 * 32 + gate * 8;
            *(float4*)dst = v0;
            *(float4*)(dst + 4) = v1;
        }

        // control thread: dataflow-gated TMA pipeline over 16 chunks.
        if (tid == 0) {
            const char* src = (const char*)g_hA[t & 1];
            unsigned need = 8u * (unsigned)t;  // producers of image[t&1] signaled
            // prologue: chunks 0,1 -> buffers 0,1
#pragma unroll
            for (int b = 0; b < 2; b++) {
                if (need) while (*(volatile unsigned*)&g_cready[b] < need) {}
                uint32_t full = sbase + 8 + b * 8;
                mbar_expect_tx(full, 16384);
                bulk_g2s(sbase + RA_OFF + b * 16384, src + (size_t)b * 16384, 16384, full);
            }
            for (int k = 0; k < 16; k++) {
                int b = k & 3;
                // prefetch chunk k+2 into buffer (k+2)&3
                if (k + 2 < 16) {
                    int cn = k + 2, bn2 = cn & 3;
                    if (need) while (*(volatile unsigned*)&g_cready[cn] < need) {}
                    if (cn >= 4) mbar_wait(sbase + 40 + bn2 * 8, ((k - 2) >> 2) & 1);
                    uint32_t full = sbase + 8 + bn2 * 8;
                    mbar_expect_tx(full, 16384);
                    bulk_g2s(sbase + RA_OFF + bn2 * 16384,
                             src + (size_t)cn * 16384, 16384, full);
                }
                // consume chunk k
                mbar_wait(sbase + 8 + b * 8, (k >> 2) & 1);
                uint64_t ad = MK_DESC(sbase + RA_OFF + b * 16384);
                uint64_t bd0 = MK_DESC(sbase + RW_OFF + k * 4096);
                uint64_t bd1 = MK_DESC(sbase + RW_OFF + (k + 16) * 4096);
#pragma unroll
                for (int j = 0; j < 4; j++)
                    mma_f16_ss(tmem, ad + j * 2, bd0 + j * 2, REC_IDESC,
                               (k > 0 || j > 0) ? 1u : 0u);
#pragma unroll
                for (int j = 0; j < 4; j++)
                    mma_f16_ss(tmem, ad + j * 2, bd1 + j * 2, REC_IDESC, 1u);
                tc_commit(sbase + 40 + b * 8);
            }
            tc_commit(sbase + 72);  // ONE flip per step
        }

        // all threads: once-per-step wait, parity t&1
        mbar_wait(sbase + 72, t & 1);
        asm volatile("tcgen05.fence::after_thread_sync;" ::: "memory");
        uint32_t rr[32];
        if (wid < 4) {
            LDTM_X32(rr, tmem);
            asm volatile("tcgen05.wait::ld.sync.aligned;" ::: "memory");
        }
        if (wid >= 2 && wid < 4) {
            int m = (wid - 2) * 32 + lane;
            float* lr = loD + m * 33;
#pragma unroll
            for (int j = 0; j < 32; j++) lr[j] = __uint_as_float(rr[j]);
        }
        __syncthreads();
        if (wid < 2) {
            int m = m_ep;
            const float* lr = loD + m * 33;
            float hv[8];
#pragma unroll
            for (int u = 0; u < 8; u++) {
                float gi = __uint_as_float(rr[u]) + lr[u] + gxs[m * 32 + u];
                float gf = __uint_as_float(rr[8 + u]) + lr[8 + u] + gxs[m * 32 + 8 + u];
                float go = __uint_as_float(rr[16 + u]) + lr[16 + u] + gxs[m * 32 + 16 + u];
                float gg = __uint_as_float(rr[24 + u]) + lr[24 + u] + gxs[m * 32 + 24 + u];
                float si = 1.f / (1.f + __expf(-gi));
                float sf = 1.f / (1.f + __expf(-gf));
                float so = 1.f / (1.f + __expf(-go));
                float cn = sf * creg[u] + si * tanhf(gg);
                creg[u] = cn;
                hv[u] = so * tanhf(cn);
            }
            float* op = outp + ((size_t)m * SS + t) * HH + jb;
            float4 o0 = {hv[0], hv[1], hv[2], hv[3]};
            float4 o1 = {hv[4], hv[5], hv[6], hv[7]};
            *(float4*)op = o0;
            *(float4*)(op + 4) = o1;
            uint32_t hp[4], lp[4];
#pragma unroll
            for (int q = 0; q < 4; q++) {
                __nv_bfloat16 b0 = __float2bfloat16(hv[2 * q]);
                __nv_bfloat16 b1 = __float2bfloat16(hv[2 * q + 1]);
                __nv_bfloat16 c0 = __float2bfloat16(hv[2 * q] - __bfloat162float(b0));
                __nv_bfloat16 c1 = __float2bfloat16(hv[2 * q + 1] - __bfloat162float(b1));
                hp[q] = (uint32_t)__bfloat16_as_ushort(b0) |
                        ((uint32_t)__bfloat16_as_ushort(b1) << 16);
                lp[q] = (uint32_t)__bfloat16_as_ushort(c0) |
                        ((uint32_t)__bfloat16_as_ushort(c1) << 16);
            }
            char* img = (char*)g_hA[(t + 1) & 1] + (size_t)wchunk * 16384;
            *(uint4*)(img + (SWZ((uint32_t)m * 128) ^ wc_hi)) = *(uint4*)hp;
            *(uint4*)(img + (SWZ((uint32_t)(m + 64) * 128) ^ wc_hi)) = *(uint4*)lp;
            if (t == SS - 1) {
#pragma unroll
                for (int u = 0; u < 8; u++) {
                    g_hfin[(size_t)m * HH + jb + u] = hv[u];
                    g_cfin[(size_t)m * HH + jb + u] = creg[u];
                }
            }
        }
        // producer signal: h-image chunk (cta>>3) for step t+1 is written
        __syncthreads();
        if (tid == 0) {
            __threadfence();
            atomicAdd(&g_cready[cta >> 3], 1u);
        }
    }
    __syncthreads();
    if (wid == 0) {
        asm volatile("tcgen05.dealloc.cta_group::1.sync.aligned.b32 %0, %1;"
                     :: "r"(tmem), "r"(32));
    }
#else
    // SIMT fallback (never selected at runtime on GB300; correctness-preserving).
    int tid = threadIdx.x;
    int cta = blockIdx.x;
    int jb = cta * 8;
    __shared__ float cs[512];
    __shared__ float hb2[512];
    for (int i = tid; i < 512; i += RNTHR) cs[i] = 0.f;
    __syncthreads();
    for (int t = 0; t < SS; t++) {
        const __nv_bfloat16* hin = g_hsp[t & 1];
        __nv_bfloat16* hout = g_hsp[(t + 1) & 1];
        const float* gxt = g_gx + (size_t)t * BB * G4H;
        for (int e = tid; e < 512; e += RNTHR) {
            int m = e >> 3, u = e & 7;
            float g4[4];
            for (int gate = 0; gate < 4; gate++) {
                const __nv_bfloat16* arow = hin + (size_t)m * KHP2;
                const __nv_bfloat16* brow = g_bh + (size_t)(cta * 32 + gate * 8 + u) * KHP2;
                float acc = 0.f;
                for (int k = 0; k < 1024; k++) {
                    float ahv = __bfloat162float(arow[k]);
                    float alv = __bfloat162float(arow[1024 + k]);
                    float wh = __bfloat162float(brow[k]);
                    float wl = __bfloat162float(brow[1024 + k]);
                    acc += (ahv + alv) * (wh + wl);
                }
                g4[gate] = acc + gxt[(size_t)m * G4H + gate * HH + jb + u];
            }
            float si = 1.f / (1.f + __expf(-g4[0]));
            float sf = 1.f / (1.f + __expf(-g4[1]));
            float so = 1.f / (1.f + __expf(-g4[2]));
            float cn = sf * cs[e] + si * tanhf(g4[3]);
            cs[e] = cn;
            float h = so * tanhf(cn);
            hb2[e] = h;
            outp[((size_t)m * SS + t) * HH + jb + u] = h;
            if (t == SS - 1) {
                g_hfin[(size_t)m * HH + jb + u] = h;
                g_cfin[(size_t)m * HH + jb + u] = cn;
            }
        }
        grid_bar();
        for (int e = tid; e < 512; e += RNTHR) {
            int m = e >> 3, u = e & 7;
            float h = hb2[e];
            __nv_bfloat16 hb = __float2bfloat16(h);
            __nv_bfloat16 lb = __float2bfloat16(h - __bfloat162float(hb));
            hout[(size_t)m * KHP2 + jb + u] = hb;
            hout[(size_t)m * KHP2 + 1024 + jb + u] = lb;
        }
        grid_bar();
    }
#endif
}

// ---------------- tail: final (h, c) leaves if present ----------------
__global__ void tail_kernel(float* __restrict__ dst, int nh, int nc) {
    int i = blockIdx.x * blockDim.x + threadIdx.x;
    if (i < nh) dst[OUT_MAIN + i] = g_hfin[i];
    if (i < nc) dst[OUT_MAIN + 65536 + i] = g_cfin[i];
}

// ---------------- launch ----------------
extern "C" void kernel_launch(void* const* d_in, const int* in_sizes, int n_in,
                              void* d_out, int out_size) {
    const float* x = nullptr;
    const float* W = nullptr;
    const float* bias = nullptr;
    for (int i = 0; i < n_in; i++) {
        if (in_sizes[i] == BB * SS * DD) x = (const float*)d_in[i];
        else if (in_sizes[i] == G4H * KW) W = (const float*)d_in[i];
        else if (in_sizes[i] == G4H) bias = (const float*)d_in[i];
    }
    float* out = (float*)d_out;

    cudaFuncSetAttribute(gemm_tc, cudaFuncAttributeMaxDynamicSharedMemorySize, GEMM_SMEM);
    cudaFuncSetAttribute(lstm_tc, cudaFuncAttributeMaxDynamicSharedMemorySize, RSMEM);

    init_kernel<<<(BB * KHP2 / 2 + 1023) / 1024, 1024>>>();
    conv_a_kernel<<<(BB * SS * 256) / 256, 256>>>(x);
    conv_b_kernel<<<(G4H * 256) / 256, 256>>>(W);
    conv_bh_kernel<<<(G4H * 256) / 256, 256>>>(W);

    gemm_tc<<<dim3(16, 256), 128, GEMM_SMEM>>>(bias);

    lstm_tc<<<RNBLK, RNTHR, RSMEM>>>(out);

    if (out_size > OUT_MAIN) {
        int extra = out_size - OUT_MAIN;
        int nh = extra < 65536 ? extra : 65536;
        int nc = extra > 65536 ? (extra - 65536 < 65536 ? extra - 65536 : 65536) : 0;
        tail_kernel<<<64, 1024>>>(out, nh, nc);
    }
}

// round 16
// speedup vs baseline: 1.0332x; 1.0332x over previous
#include <cuda_runtime.h>
#include <cuda_bf16.h>
#include <math.h>
#include <stdint.h>

// Problem constants
#define BB 64
#define SS 512
#define DD 1024
#define HH 1024
#define G4H 4096          // 4*H
#define KW 2048           // D+H
#define KP 3072           // split-bf16 packed K for x-GEMM (hi|hi|lo)
#define KHP2 2048         // packed h cols: [hi | lo]
#define OUT_MAIN 33554432 // B*S*H
#define RNBLK 128
#define RNTHR 256

// tcgen05 availability: only in the arch-specific (sm_103a/sm_100a) compile pass.
#if defined(__CUDA_ARCH_FEAT_SM103_ALL) || defined(__CUDA_ARCH_FEAT_SM100_ALL) || \
    (defined(__CUDA_ARCH_SPECIFIC__) && (__CUDA_ARCH_SPECIFIC__ >= 1000))
#define HAS_TC5 1
#else
#define HAS_TC5 0
#endif

// ---------------- device scratch (no allocs allowed) ----------------
__device__ float g_gx[(size_t)SS * BB * G4H];            // [s][b][4H]
__device__ __align__(1024) __nv_bfloat16 g_a[(size_t)(BB * SS) * KP];
__device__ __align__(1024) __nv_bfloat16 g_b[(size_t)G4H * KP];
__device__ __nv_bfloat16 g_bh[(size_t)RNBLK * 32 * KHP2];// Wh' [128*32][2048] = [Whi|Wlo]
__device__ __align__(1024) __nv_bfloat16 g_hA[2][131072];// 2 x 256KB stage images
__device__ __nv_bfloat16 g_hsp[2][(size_t)BB * KHP2];    // SIMT-fallback h buffers
__device__ float g_hfin[BB * HH];
__device__ float g_cfin[BB * HH];
__device__ unsigned g_arrive;
__device__ unsigned g_epoch;

// ---------------- PTX helpers ----------------
__device__ __forceinline__ uint32_t smem_u32(const void* p) {
    uint32_t a;
    asm("{ .reg .u64 t; cvta.to.shared.u64 t, %1; cvt.u32.u64 %0, t; }" : "=r"(a) : "l"(p));
    return a;
}

#if HAS_TC5
__device__ __forceinline__ uint32_t elect1() {
    uint32_t p;
    asm volatile("{\n\t.reg .pred p;\n\telect.sync _|p, 0xFFFFFFFF;\n\tselp.b32 %0, 1, 0, p;\n\t}" : "=r"(p));
    return p;
}
__device__ __forceinline__ void mbar_init(uint32_t mbar, uint32_t cnt) {
    asm volatile("mbarrier.init.shared.b64 [%0], %1;" :: "r"(mbar), "r"(cnt) : "memory");
}
__device__ __forceinline__ void mbar_expect_tx(uint32_t mbar, uint32_t bytes) {
    asm volatile("mbarrier.arrive.expect_tx.shared.b64 _, [%0], %1;"
                 :: "r"(mbar), "r"(bytes) : "memory");
}
__device__ __forceinline__ void bulk_g2s(uint32_t dst, const void* src, uint32_t bytes,
                                         uint32_t mbar) {
    asm volatile(
        "cp.async.bulk.shared::cta.global.mbarrier::complete_tx::bytes [%0], [%1], %2, [%3];"
        :: "r"(dst), "l"(src), "r"(bytes), "r"(mbar) : "memory");
}
__device__ __forceinline__ void mbar_wait(uint32_t mbar, uint32_t parity) {
    asm volatile(
        "{\n\t.reg .pred P1;\n\t"
        "WL%=:\n\t"
        "mbarrier.try_wait.parity.acquire.cta.shared::cta.b64 P1, [%0], %1, 0x989680;\n\t"
        "@P1 bra.uni WD%=;\n\t"
        "bra.uni WL%=;\n\t"
        "WD%=:\n\t}"
        :: "r"(mbar), "r"(parity) : "memory");
}
__device__ __forceinline__ void mma_f16_ss(uint32_t d, uint64_t ad, uint64_t bd,
                                           uint32_t idesc, uint32_t en) {
    asm volatile(
        "{\n\t.reg .pred p;\n\tsetp.ne.u32 p, %5, 0;\n\t"
        "tcgen05.mma.cta_group::1.kind::f16 [%0], %1, %2, %3, {%4, %4, %4, %4}, p;\n\t}"
        :: "r"(d), "l"(ad), "l"(bd), "r"(idesc), "r"(0u), "r"(en) : "memory");
}
__device__ __forceinline__ void tc_commit(uint32_t mbar) {
    asm volatile("tcgen05.commit.cta_group::1.mbarrier::arrive::one.shared::cluster.b64 [%0];"
                 :: "r"(mbar) : "memory");
}
#define LDTM_X32(r, addr) \
    asm volatile( \
        "tcgen05.ld.sync.aligned.32x32b.x32.b32 " \
        "{%0, %1, %2, %3, %4, %5, %6, %7, %8, %9, %10, %11, %12, %13, %14, %15, " \
        " %16, %17, %18, %19, %20, %21, %22, %23, %24, %25, %26, %27, %28, %29, %30, %31}, [%32];" \
        : "=r"((r)[0]), "=r"((r)[1]), "=r"((r)[2]), "=r"((r)[3]), \
          "=r"((r)[4]), "=r"((r)[5]), "=r"((r)[6]), "=r"((r)[7]), \
          "=r"((r)[8]), "=r"((r)[9]), "=r"((r)[10]), "=r"((r)[11]), \
          "=r"((r)[12]), "=r"((r)[13]), "=r"((r)[14]), "=r"((r)[15]), \
          "=r"((r)[16]), "=r"((r)[17]), "=r"((r)[18]), "=r"((r)[19]), \
          "=r"((r)[20]), "=r"((r)[21]), "=r"((r)[22]), "=r"((r)[23]), \
          "=r"((r)[24]), "=r"((r)[25]), "=r"((r)[26]), "=r"((r)[27]), \
          "=r"((r)[28]), "=r"((r)[29]), "=r"((r)[30]), "=r"((r)[31]) \
        : "r"(addr))
#endif  // HAS_TC5

static constexpr uint64_t DESC_BASE_SW128 =
    (2ULL << 61) | (1ULL << 46) | (64ULL << 32) | (1ULL << 16);
#define MK_DESC(a) (DESC_BASE_SW128 | (((uint64_t)((a) >> 4)) & 0x3FFF))
#define SWZ(o) ((o) ^ (((o) >> 3) & 0x70))

// idesc: kind::f16, dtype=F32, a/b=BF16
#define GEMM_IDESC ((1u << 4) | (1u << 7) | (1u << 10) | ((256u / 8u) << 17) | ((128u / 16u) << 24))
// M=128, N=32 — identical to the validated test_mma.cu config (0x8080490)
#define REC_IDESC  ((1u << 4) | (1u << 7) | (1u << 10) | ((32u / 8u) << 17) | ((128u / 16u) << 24))

// fast tanh via MUFU ex2-based __expf; overflow-safe (e>=1 so no NaN)
__device__ __forceinline__ float fast_tanh(float x) {
    float ax = fabsf(x);
    float e = __expf(2.f * ax);
    float r = 1.f - 2.f / (e + 1.f);
    return copysignf(r, x);
}

// ---------------- init: zero h0 images ----------------
__global__ void init_kernel() {
    int i = blockIdx.x * blockDim.x + threadIdx.x;
    if (i < 65536) ((uint32_t*)g_hA[0])[i] = 0u;
    if (i < (BB * KHP2) / 2) ((uint32_t*)g_hsp[0])[i] = 0u;
}

// ---------------- split-bf16 conversion ----------------
__device__ __forceinline__ void split4(float4 v, uint2& hq, uint2& lq) {
    __nv_bfloat16 h0 = __float2bfloat16(v.x), h1 = __float2bfloat16(v.y);
    __nv_bfloat16 h2 = __float2bfloat16(v.z), h3 = __float2bfloat16(v.w);
    __nv_bfloat16 l0 = __float2bfloat16(v.x - __bfloat162float(h0));
    __nv_bfloat16 l1 = __float2bfloat16(v.y - __bfloat162float(h1));
    __nv_bfloat16 l2 = __float2bfloat16(v.z - __bfloat162float(h2));
    __nv_bfloat16 l3 = __float2bfloat16(v.w - __bfloat162float(h3));
    hq.x = (uint32_t)__bfloat16_as_ushort(h0) | ((uint32_t)__bfloat16_as_ushort(h1) << 16);
    hq.y = (uint32_t)__bfloat16_as_ushort(h2) | ((uint32_t)__bfloat16_as_ushort(h3) << 16);
    lq.x = (uint32_t)__bfloat16_as_ushort(l0) | ((uint32_t)__bfloat16_as_ushort(l1) << 16);
    lq.y = (uint32_t)__bfloat16_as_ushort(l2) | ((uint32_t)__bfloat16_as_ushort(l3) << 16);
}

// tiled destination byte offset inside g_a: tile row r (0..127), packed col kp
__device__ __forceinline__ size_t a_off(int bm, int r, int kp) {
    int s = kp >> 6, c = kp & 63;
    return ((size_t)(bm * 48 + s) << 14) + SWZ((uint32_t)(r * 128 + c * 2));
}
// tiled destination byte offset inside g_b: tile row r (0..255), packed col kp
__device__ __forceinline__ size_t b_off(int bn, int r, int kp) {
    int s = kp >> 6, c = kp & 63;
    return ((size_t)(bn * 48 + s) << 15) + SWZ((uint32_t)(r * 128 + c * 2));
}

// ---------------- FUSED conversions (one launch) ----------------
// blocks [0, 32768): A' = [hi|hi|lo] from x rows
// blocks [32768, 36864): B' = [hi|lo|hi] from W x-part
// blocks [36864, 40960): Wh' packed [Whi|Wlo] from W h-part
__global__ __launch_bounds__(256) void conv_all_kernel(const float* __restrict__ x,
                                                       const float* __restrict__ W) {
    int bid = blockIdx.x;
    int kq = threadIdx.x << 2;
    if (bid < 32768) {
        int m = bid;
        float4 v = *(const float4*)(x + (size_t)m * DD + kq);
        uint2 hq, lq;
        split4(v, hq, lq);
        int bm = m >> 7, r = m & 127;
        char* base = (char*)g_a;
        *(uint2*)(base + a_off(bm, r, kq)) = hq;
        *(uint2*)(base + a_off(bm, r, 1024 + kq)) = hq;
        *(uint2*)(base + a_off(bm, r, 2048 + kq)) = lq;
    } else if (bid < 36864) {
        int n = bid - 32768;
        float4 v = *(const float4*)(W + (size_t)n * KW + kq);
        uint2 hq, lq;
        split4(v, hq, lq);
        int bn = n >> 8, r = n & 255;
        char* base = (char*)g_b;
        *(uint2*)(base + b_off(bn, r, kq)) = hq;
        *(uint2*)(base + b_off(bn, r, 1024 + kq)) = lq;
        *(uint2*)(base + b_off(bn, r, 2048 + kq)) = hq;
    } else {
        int n = bid - 36864;
        float4 v = *(const float4*)(W + (size_t)n * KW + DD + kq);
        uint2 hq, lq;
        split4(v, hq, lq);
        int gate = n >> 10, j = n & 1023;
        int rp = (j >> 3) * 32 + gate * 8 + (j & 7);
        char* base = (char*)(g_bh + (size_t)rp * KHP2 + kq);
        *(uint2*)(base) = hq;
        *(uint2*)(base + 1024 * 2) = lq;
    }
}

// ---------------- tcgen05 x-GEMM (unchanged from R8) --------
#define GSTG 49152
#define GEMM_SMEM (1024 + 4 * GSTG)  // 197632
__global__ __launch_bounds__(128, 1) void gemm_tc(const float* __restrict__ bias) {
#if HAS_TC5
    extern __shared__ __align__(1024) char smem[];
    uint32_t sbase = smem_u32(smem);
    int tid = threadIdx.x;
    int wid = tid >> 5, lane = tid & 31;
    int bn = blockIdx.x;  // 0..15
    int bm = blockIdx.y;  // 0..255

    if (wid == 0) {
        asm volatile("tcgen05.alloc.cta_group::1.sync.aligned.shared::cta.b32 [%0], %1;"
                     :: "r"(sbase), "r"(256) : "memory");
        asm volatile("tcgen05.relinquish_alloc_permit.cta_group::1.sync.aligned;");
    }
    if (tid == 0) {
#pragma unroll
        for (int i = 0; i < 4; i++) {
            mbar_init(sbase + 8 + i * 8, 1);
            mbar_init(sbase + 40 + i * 8, 1);
        }
        mbar_init(sbase + 72, 1);
    }
    __syncthreads();
    uint32_t tmem;
    asm volatile("ld.shared.b32 %0, [%1];" : "=r"(tmem) : "r"(sbase));

    const char* Asrc = (const char*)g_a + ((size_t)bm * 48 << 14);
    const char* Bsrc = (const char*)g_b + ((size_t)bn * 48 << 15);

    if (tid == 0) {
#pragma unroll
        for (int s = 0; s < 4; s++) {
            uint32_t full = sbase + 8 + s * 8;
            uint32_t dst = sbase + 1024 + s * GSTG;
            mbar_expect_tx(full, GSTG);
            bulk_g2s(dst, Asrc + (size_t)s * 16384, 16384, full);
            bulk_g2s(dst + 16384, Bsrc + (size_t)s * 32768, 32768, full);
        }
        for (int s = 0; s < 48; s++) {
            int b = s & 3;
            uint32_t p = (s >> 2) & 1;
            mbar_wait(sbase + 8 + b * 8, p);
            uint64_t ad = MK_DESC(sbase + 1024 + b * GSTG);
            uint64_t bd = MK_DESC(sbase + 1024 + b * GSTG + 16384);
#pragma unroll
            for (int k = 0; k < 4; k++)
                mma_f16_ss(tmem, ad + k * 2, bd + k * 2, GEMM_IDESC,
                           (s > 0 || k > 0) ? 1u : 0u);
            tc_commit(sbase + 40 + b * 8);
            if (s + 4 < 48) {
                mbar_wait(sbase + 40 + b * 8, p);
                int sn = s + 4;
                uint32_t full = sbase + 8 + b * 8;
                uint32_t dst = sbase + 1024 + b * GSTG;
                mbar_expect_tx(full, GSTG);
                bulk_g2s(dst, Asrc + (size_t)sn * 16384, 16384, full);
                bulk_g2s(dst + 16384, Bsrc + (size_t)sn * 32768, 32768, full);
            }
        }
        tc_commit(sbase + 72);
    }
    mbar_wait(sbase + 72, 0);
    asm volatile("tcgen05.fence::after_thread_sync;" ::: "memory");

    {
        int m = bm * 128 + wid * 32 + lane;
        int s_ = m & 511, b_ = m >> 9;
        float* orow = g_gx + (size_t)(s_ * BB + b_) * G4H + bn * 256;
        const float* brow = bias + bn * 256;
#pragma unroll 1
        for (int cb = 0; cb < 256; cb += 32) {
            uint32_t r[32];
            LDTM_X32(r, tmem + cb);
            asm volatile("tcgen05.wait::ld.sync.aligned;" ::: "memory");
#pragma unroll
            for (int j = 0; j < 32; j += 4) {
                float4 v;
                v.x = __uint_as_float(r[j + 0]) + __ldg(brow + cb + j + 0);
                v.y = __uint_as_float(r[j + 1]) + __ldg(brow + cb + j + 1);
                v.z = __uint_as_float(r[j + 2]) + __ldg(brow + cb + j + 2);
                v.w = __uint_as_float(r[j + 3]) + __ldg(brow + cb + j + 3);
                *(float4*)(orow + cb + j) = v;
            }
        }
    }
    __syncthreads();
    if (wid == 0) {
        asm volatile("tcgen05.dealloc.cta_group::1.sync.aligned.b32 %0, %1;"
                     :: "r"(tmem), "r"(256));
    }
#else
    int tid = threadIdx.x;
    int bn = blockIdx.x, bm = blockIdx.y;
    const char* ab = (const char*)g_a;
    const char* bb = (const char*)g_b;
    for (int idx = tid; idx < 128 * 256; idx += 128) {
        int mi = idx >> 8, ni = idx & 255;
        float acc = 0.f;
        for (int kp = 0; kp < KP; kp++) {
            __nv_bfloat16 av = *(const __nv_bfloat16*)(ab + a_off(bm, mi, kp));
            __nv_bfloat16 bv = *(const __nv_bfloat16*)(bb + b_off(bn, ni, kp));
            acc += __bfloat162float(av) * __bfloat162float(bv);
        }
        int m = bm * 128 + mi, n = bn * 256 + ni;
        int s_ = m & 511, b_ = m >> 9;
        g_gx[(size_t)(s_ * BB + b_) * G4H + n] = acc + bias[n];
    }
#endif
}

// ---------------- grid barrier (atomic, known-good) ----------------
__device__ __forceinline__ void grid_bar() {
    __syncthreads();
    if (threadIdx.x == 0) {
        __threadfence();
        unsigned e = g_epoch;
        unsigned old = atomicAdd(&g_arrive, 1);
        if (old == RNBLK - 1) {
            g_arrive = 0;
            __threadfence();
            atomicExch(&g_epoch, e + 1);
        } else {
            while (*(volatile unsigned*)&g_epoch == e) {}
            __threadfence();
        }
    }
    __syncthreads();
}

// ---------------- persistent tcgen05 recurrent kernel (R13 winner + fast_tanh) ---
#define RW_OFF 1024
#define RA_OFF (RW_OFF + 131072)    // 132096, 4 x 16384
#define RGX_OFF (RA_OFF + 65536)    // 197632
#define RLO_OFF (RGX_OFF + 8192)    // 205824
#define RSMEM (RLO_OFF + 8448)      // 214272
__global__ __launch_bounds__(RNTHR, 1) void lstm_tc(float* __restrict__ outp) {
#if HAS_TC5
    extern __shared__ __align__(1024) char smem[];
    uint32_t sbase = smem_u32(smem);
    int tid = threadIdx.x, wid = tid >> 5, lane = tid & 31;
    int cta = blockIdx.x;
    int jb = cta * 8;

    if (wid == 0) {
        asm volatile("tcgen05.alloc.cta_group::1.sync.aligned.shared::cta.b32 [%0], %1;"
                     :: "r"(sbase), "r"(32) : "memory");
        asm volatile("tcgen05.relinquish_alloc_permit.cta_group::1.sync.aligned;");
    }
    if (tid == 0) {
#pragma unroll
        for (int i = 0; i < 4; i++) {
            mbar_init(sbase + 8 + i * 8, 1);
            mbar_init(sbase + 40 + i * 8, 1);
        }
        mbar_init(sbase + 72, 1);
    }
    __syncthreads();
    uint32_t tmem;
    asm volatile("ld.shared.b32 %0, [%1];" : "=r"(tmem) : "r"(sbase));

    // Load resident Wh' slice: 32 chunks x (32 rows x 128B), SW128 swizzled.
    {
        const __nv_bfloat16* wsrc = g_bh + (size_t)cta * 32 * KHP2;
        for (int i = tid; i < 8192; i += RNTHR) {
            int lc = i >> 8, q = i & 255;
            uint4 v = *(const uint4*)(wsrc + (size_t)lc * KHP2 + q * 8);
            int c = q >> 3;
            uint32_t off = (uint32_t)lc * 128 + (q & 7) * 16;
            *(uint4*)(smem + RW_OFF + c * 4096 + SWZ(off)) = v;
        }
    }
    __syncthreads();

    float* gxs = (float*)(smem + RGX_OFF);
    float* loD = (float*)(smem + RLO_OFF);
    float creg[8];
#pragma unroll
    for (int u = 0; u < 8; u++) creg[u] = 0.f;
    int m_ep = wid * 32 + lane;

    int wchunk = jb >> 6;
    uint32_t wc_hi = SWZ((uint32_t)(jb & 63) * 2);

    for (int t = 0; t < SS; t++) {
        // stage Gx(t) into smem
        {
            int b2 = tid >> 2, gate = tid & 3;
            const float* src = g_gx + (size_t)t * BB * G4H + (size_t)b2 * G4H +
                               gate * HH + jb;
            float4 v0 = *(const float4*)src;
            float4 v1 = *(const float4*)(src + 4);
            float* dst = gxs + b2 * 32 + gate * 8;
            *(float4*)dst = v0;
            *(float4*)(dst + 4) = v1;
        }
        __syncthreads();

        // single control thread: 4-deep TMA pipeline over 16 chunks.
        if (tid == 0) {
            const char* src = (const char*)g_hA[t & 1];
#pragma unroll
            for (int b = 0; b < 4; b++) {
                uint32_t full = sbase + 8 + b * 8;
                mbar_expect_tx(full, 16384);
                bulk_g2s(sbase + RA_OFF + b * 16384, src + (size_t)b * 16384, 16384, full);
            }
            for (int k = 0; k < 16; k++) {
                int b = k & 3;
                uint32_t par = (k >> 2) & 1;
                mbar_wait(sbase + 8 + b * 8, par);
                uint64_t ad = MK_DESC(sbase + RA_OFF + b * 16384);
                uint64_t bd0 = MK_DESC(sbase + RW_OFF + k * 4096);
                uint64_t bd1 = MK_DESC(sbase + RW_OFF + (k + 16) * 4096);
#pragma unroll
                for (int j = 0; j < 4; j++)
                    mma_f16_ss(tmem, ad + j * 2, bd0 + j * 2, REC_IDESC,
                               (k > 0 || j > 0) ? 1u : 0u);
#pragma unroll
                for (int j = 0; j < 4; j++)
                    mma_f16_ss(tmem, ad + j * 2, bd1 + j * 2, REC_IDESC, 1u);
                tc_commit(sbase + 40 + b * 8);
                if (k + 4 < 16) {
                    mbar_wait(sbase + 40 + b * 8, par);
                    uint32_t full = sbase + 8 + b * 8;
                    mbar_expect_tx(full, 16384);
                    bulk_g2s(sbase + RA_OFF + b * 16384,
                             src + (size_t)(k + 4) * 16384, 16384, full);
                }
            }
            tc_commit(sbase + 72);  // ONE flip per step
        }

        // all threads: once-per-step wait, parity t&1
        mbar_wait(sbase + 72, t & 1);
        asm volatile("tcgen05.fence::after_thread_sync;" ::: "memory");
        uint32_t rr[32];
        if (wid < 4) {
            LDTM_X32(rr, tmem);
            asm volatile("tcgen05.wait::ld.sync.aligned;" ::: "memory");
        }
        if (wid >= 2 && wid < 4) {
            int m = (wid - 2) * 32 + lane;
            float* lr = loD + m * 33;
#pragma unroll
            for (int j = 0; j < 32; j++) lr[j] = __uint_as_float(rr[j]);
        }
        __syncthreads();
        if (wid < 2) {
            int m = m_ep;
            const float* lr = loD + m * 33;
            float hv[8];
#pragma unroll
            for (int u = 0; u < 8; u++) {
                float gi = __uint_as_float(rr[u]) + lr[u] + gxs[m * 32 + u];
                float gf = __uint_as_float(rr[8 + u]) + lr[8 + u] + gxs[m * 32 + 8 + u];
                float go = __uint_as_float(rr[16 + u]) + lr[16 + u] + gxs[m * 32 + 16 + u];
                float gg = __uint_as_float(rr[24 + u]) + lr[24 + u] + gxs[m * 32 + 24 + u];
                float si = 1.f / (1.f + __expf(-gi));
                float sf = 1.f / (1.f + __expf(-gf));
                float so = 1.f / (1.f + __expf(-go));
                float cn = sf * creg[u] + si * fast_tanh(gg);
                creg[u] = cn;
                hv[u] = so * fast_tanh(cn);
            }
            float* op = outp + ((size_t)m * SS + t) * HH + jb;
            float4 o0 = {hv[0], hv[1], hv[2], hv[3]};
            float4 o1 = {hv[4], hv[5], hv[6], hv[7]};
            *(float4*)op = o0;
            *(float4*)(op + 4) = o1;
            uint32_t hp[4], lp[4];
#pragma unroll
            for (int q = 0; q < 4; q++) {
                __nv_bfloat16 b0 = __float2bfloat16(hv[2 * q]);
                __nv_bfloat16 b1 = __float2bfloat16(hv[2 * q + 1]);
                __nv_bfloat16 c0 = __float2bfloat16(hv[2 * q] - __bfloat162float(b0));
                __nv_bfloat16 c1 = __float2bfloat16(hv[2 * q + 1] - __bfloat162float(b1));
                hp[q] = (uint32_t)__bfloat16_as_ushort(b0) |
                        ((uint32_t)__bfloat16_as_ushort(b1) << 16);
                lp[q] = (uint32_t)__bfloat16_as_ushort(c0) |
                        ((uint32_t)__bfloat16_as_ushort(c1) << 16);
            }
            char* img = (char*)g_hA[(t + 1) & 1] + (size_t)wchunk * 16384;
            *(uint4*)(img + (SWZ((uint32_t)m * 128) ^ wc_hi)) = *(uint4*)hp;
            *(uint4*)(img + (SWZ((uint32_t)(m + 64) * 128) ^ wc_hi)) = *(uint4*)lp;
            if (t == SS - 1) {
#pragma unroll
                for (int u = 0; u < 8; u++) {
                    g_hfin[(size_t)m * HH + jb + u] = hv[u];
                    g_cfin[(size_t)m * HH + jb + u] = creg[u];
                }
            }
        }
        grid_bar();
    }
    __syncthreads();
    if (wid == 0) {
        asm volatile("tcgen05.dealloc.cta_group::1.sync.aligned.b32 %0, %1;"
                     :: "r"(tmem), "r"(32));
    }
#else
    // SIMT fallback (never selected at runtime on GB300; correctness-preserving).
    int tid = threadIdx.x;
    int cta = blockIdx.x;
    int jb = cta * 8;
    __shared__ float cs[512];
    __shared__ float hb2[512];
    for (int i = tid; i < 512; i += RNTHR) cs[i] = 0.f;
    __syncthreads();
    for (int t = 0; t < SS; t++) {
        const __nv_bfloat16* hin = g_hsp[t & 1];
        __nv_bfloat16* hout = g_hsp[(t + 1) & 1];
        const float* gxt = g_gx + (size_t)t * BB * G4H;
        for (int e = tid; e < 512; e += RNTHR) {
            int m = e >> 3, u = e & 7;
            float g4[4];
            for (int gate = 0; gate < 4; gate++) {
                const __nv_bfloat16* arow = hin + (size_t)m * KHP2;
                const __nv_bfloat16* brow = g_bh + (size_t)(cta * 32 + gate * 8 + u) * KHP2;
                float acc = 0.f;
                for (int k = 0; k < 1024; k++) {
                    float ahv = __bfloat162float(arow[k]);
                    float alv = __bfloat162float(arow[1024 + k]);
                    float wh = __bfloat162float(brow[k]);
                    float wl = __bfloat162float(brow[1024 + k]);
                    acc += (ahv + alv) * (wh + wl);
                }
                g4[gate] = acc + gxt[(size_t)m * G4H + gate * HH + jb + u];
            }
            float si = 1.f / (1.f + __expf(-g4[0]));
            float sf = 1.f / (1.f + __expf(-g4[1]));
            float so = 1.f / (1.f + __expf(-g4[2]));
            float cn = sf * cs[e] + si * tanhf(g4[3]);
            cs[e] = cn;
            float h = so * tanhf(cn);
            hb2[e] = h;
            outp[((size_t)m * SS + t) * HH + jb + u] = h;
            if (t == SS - 1) {
                g_hfin[(size_t)m * HH + jb + u] = h;
                g_cfin[(size_t)m * HH + jb + u] = cn;
            }
        }
        grid_bar();
        for (int e = tid; e < 512; e += RNTHR) {
            int m = e >> 3, u = e & 7;
            float h = hb2[e];
            __nv_bfloat16 hb = __float2bfloat16(h);
            __nv_bfloat16 lb = __float2bfloat16(h - __bfloat162float(hb));
            hout[(size_t)m * KHP2 + jb + u] = hb;
            hout[(size_t)m * KHP2 + 1024 + jb + u] = lb;
        }
        grid_bar();
    }
#endif
}

// ---------------- tail: final (h, c) leaves if present ----------------
__global__ void tail_kernel(float* __restrict__ dst, int nh, int nc) {
    int i = blockIdx.x * blockDim.x + threadIdx.x;
    if (i < nh) dst[OUT_MAIN + i] = g_hfin[i];
    if (i < nc) dst[OUT_MAIN + 65536 + i] = g_cfin[i];
}

// ---------------- launch ----------------
extern "C" void kernel_launch(void* const* d_in, const int* in_sizes, int n_in,
                              void* d_out, int out_size) {
    const float* x = nullptr;
    const float* W = nullptr;
    const float* bias = nullptr;
    for (int i = 0; i < n_in; i++) {
        if (in_sizes[i] == BB * SS * DD) x = (const float*)d_in[i];
        else if (in_sizes[i] == G4H * KW) W = (const float*)d_in[i];
        else if (in_sizes[i] == G4H) bias = (const float*)d_in[i];
    }
    float* out = (float*)d_out;

    cudaFuncSetAttribute(gemm_tc, cudaFuncAttributeMaxDynamicSharedMemorySize, GEMM_SMEM);
    cudaFuncSetAttribute(lstm_tc, cudaFuncAttributeMaxDynamicSharedMemorySize, RSMEM);

    init_kernel<<<64, 1024>>>();
    conv_all_kernel<<<40960, 256>>>(x, W);

    gemm_tc<<<dim3(16, 256), 128, GEMM_SMEM>>>(bias);

    lstm_tc<<<RNBLK, RNTHR, RSMEM>>>(out);   // 4th launch -> ncu capture window

    if (out_size > OUT_MAIN) {
        int extra = out_size - OUT_MAIN;
        int nh = extra < 65536 ? extra : 65536;
        int nc = extra > 65536 ? (extra - 65536 < 65536 ? extra - 65536 : 65536) : 0;
        tail_kernel<<<64, 1024>>>(out, nh, nc);
    }
}

// round 17
// speedup vs baseline: 1.1845x; 1.1465x over previous
#include <cuda_runtime.h>
#include <cuda_bf16.h>
#include <math.h>
#include <stdint.h>

// Problem constants
#define BB 64
#define SS 512
#define DD 1024
#define HH 1024
#define G4H 4096          // 4*H
#define KW 2048           // D+H
#define KP 3072           // split-bf16 packed K for x-GEMM (hi|hi|lo)
#define KHP2 2048         // packed h cols: [hi | lo]
#define OUT_MAIN 33554432 // B*S*H
#define RNBLK 128
#define RNTHR 256

// tcgen05 availability: only in the arch-specific (sm_103a/sm_100a) compile pass.
#if defined(__CUDA_ARCH_FEAT_SM103_ALL) || defined(__CUDA_ARCH_FEAT_SM100_ALL) || \
    (defined(__CUDA_ARCH_SPECIFIC__) && (__CUDA_ARCH_SPECIFIC__ >= 1000))
#define HAS_TC5 1
#else
#define HAS_TC5 0
#endif

// ---------------- device scratch (no allocs allowed) ----------------
__device__ float g_gx[(size_t)SS * BB * G4H];            // [s][b][4H]
__device__ __align__(1024) __nv_bfloat16 g_a[(size_t)(BB * SS) * KP];
__device__ __align__(1024) __nv_bfloat16 g_b[(size_t)G4H * KP];
__device__ __nv_bfloat16 g_bh[(size_t)RNBLK * 32 * KHP2];// Wh' [128*32][2048] = [Whi|Wlo]
__device__ __align__(1024) __nv_bfloat16 g_hA[2][131072];// 2 x 256KB stage images
__device__ __nv_bfloat16 g_hsp[2][(size_t)BB * KHP2];    // SIMT-fallback h buffers
__device__ float g_hfin[BB * HH];
__device__ float g_cfin[BB * HH];
__device__ unsigned g_arrive;
__device__ unsigned g_epoch;

// ---------------- PTX helpers ----------------
__device__ __forceinline__ uint32_t smem_u32(const void* p) {
    uint32_t a;
    asm("{ .reg .u64 t; cvta.to.shared.u64 t, %1; cvt.u32.u64 %0, t; }" : "=r"(a) : "l"(p));
    return a;
}

#if HAS_TC5
__device__ __forceinline__ uint32_t elect1() {
    uint32_t p;
    asm volatile("{\n\t.reg .pred p;\n\telect.sync _|p, 0xFFFFFFFF;\n\tselp.b32 %0, 1, 0, p;\n\t}" : "=r"(p));
    return p;
}
__device__ __forceinline__ void mbar_init(uint32_t mbar, uint32_t cnt) {
    asm volatile("mbarrier.init.shared.b64 [%0], %1;" :: "r"(mbar), "r"(cnt) : "memory");
}
__device__ __forceinline__ void mbar_expect_tx(uint32_t mbar, uint32_t bytes) {
    asm volatile("mbarrier.arrive.expect_tx.shared.b64 _, [%0], %1;"
                 :: "r"(mbar), "r"(bytes) : "memory");
}
__device__ __forceinline__ void bulk_g2s(uint32_t dst, const void* src, uint32_t bytes,
                                         uint32_t mbar) {
    asm volatile(
        "cp.async.bulk.shared::cta.global.mbarrier::complete_tx::bytes [%0], [%1], %2, [%3];"
        :: "r"(dst), "l"(src), "r"(bytes), "r"(mbar) : "memory");
}
__device__ __forceinline__ void mbar_wait(uint32_t mbar, uint32_t parity) {
    asm volatile(
        "{\n\t.reg .pred P1;\n\t"
        "WL%=:\n\t"
        "mbarrier.try_wait.parity.acquire.cta.shared::cta.b64 P1, [%0], %1, 0x989680;\n\t"
        "@P1 bra.uni WD%=;\n\t"
        "bra.uni WL%=;\n\t"
        "WD%=:\n\t}"
        :: "r"(mbar), "r"(parity) : "memory");
}
__device__ __forceinline__ void mma_f16_ss(uint32_t d, uint64_t ad, uint64_t bd,
                                           uint32_t idesc, uint32_t en) {
    asm volatile(
        "{\n\t.reg .pred p;\n\tsetp.ne.u32 p, %5, 0;\n\t"
        "tcgen05.mma.cta_group::1.kind::f16 [%0], %1, %2, %3, {%4, %4, %4, %4}, p;\n\t}"
        :: "r"(d), "l"(ad), "l"(bd), "r"(idesc), "r"(0u), "r"(en) : "memory");
}
__device__ __forceinline__ void tc_commit(uint32_t mbar) {
    asm volatile("tcgen05.commit.cta_group::1.mbarrier::arrive::one.shared::cluster.b64 [%0];"
                 :: "r"(mbar) : "memory");
}
#define LDTM_X32(r, addr) \
    asm volatile( \
        "tcgen05.ld.sync.aligned.32x32b.x32.b32 " \
        "{%0, %1, %2, %3, %4, %5, %6, %7, %8, %9, %10, %11, %12, %13, %14, %15, " \
        " %16, %17, %18, %19, %20, %21, %22, %23, %24, %25, %26, %27, %28, %29, %30, %31}, [%32];" \
        : "=r"((r)[0]), "=r"((r)[1]), "=r"((r)[2]), "=r"((r)[3]), \
          "=r"((r)[4]), "=r"((r)[5]), "=r"((r)[6]), "=r"((r)[7]), \
          "=r"((r)[8]), "=r"((r)[9]), "=r"((r)[10]), "=r"((r)[11]), \
          "=r"((r)[12]), "=r"((r)[13]), "=r"((r)[14]), "=r"((r)[15]), \
          "=r"((r)[16]), "=r"((r)[17]), "=r"((r)[18]), "=r"((r)[19]), \
          "=r"((r)[20]), "=r"((r)[21]), "=r"((r)[22]), "=r"((r)[23]), \
          "=r"((r)[24]), "=r"((r)[25]), "=r"((r)[26]), "=r"((r)[27]), \
          "=r"((r)[28]), "=r"((r)[29]), "=r"((r)[30]), "=r"((r)[31]) \
        : "r"(addr))
#endif  // HAS_TC5

static constexpr uint64_t DESC_BASE_SW128 =
    (2ULL << 61) | (1ULL << 46) | (64ULL << 32) | (1ULL << 16);
#define MK_DESC(a) (DESC_BASE_SW128 | (((uint64_t)((a) >> 4)) & 0x3FFF))
#define SWZ(o) ((o) ^ (((o) >> 3) & 0x70))

// idesc: kind::f16, dtype=F32, a/b=BF16
#define GEMM_IDESC ((1u << 4) | (1u << 7) | (1u << 10) | ((256u / 8u) << 17) | ((128u / 16u) << 24))
// M=128, N=32 — identical to the validated test_mma.cu config (0x8080490)
#define REC_IDESC  ((1u << 4) | (1u << 7) | (1u << 10) | ((32u / 8u) << 17) | ((128u / 16u) << 24))

// ---------------- init: zero h0 images ----------------
__global__ void init_kernel() {
    int i = blockIdx.x * blockDim.x + threadIdx.x;
    if (i < 65536) ((uint32_t*)g_hA[0])[i] = 0u;
    if (i < (BB * KHP2) / 2) ((uint32_t*)g_hsp[0])[i] = 0u;
}

// ---------------- split-bf16 conversion ----------------
__device__ __forceinline__ void split4(float4 v, uint2& hq, uint2& lq) {
    __nv_bfloat16 h0 = __float2bfloat16(v.x), h1 = __float2bfloat16(v.y);
    __nv_bfloat16 h2 = __float2bfloat16(v.z), h3 = __float2bfloat16(v.w);
    __nv_bfloat16 l0 = __float2bfloat16(v.x - __bfloat162float(h0));
    __nv_bfloat16 l1 = __float2bfloat16(v.y - __bfloat162float(h1));
    __nv_bfloat16 l2 = __float2bfloat16(v.z - __bfloat162float(h2));
    __nv_bfloat16 l3 = __float2bfloat16(v.w - __bfloat162float(h3));
    hq.x = (uint32_t)__bfloat16_as_ushort(h0) | ((uint32_t)__bfloat16_as_ushort(h1) << 16);
    hq.y = (uint32_t)__bfloat16_as_ushort(h2) | ((uint32_t)__bfloat16_as_ushort(h3) << 16);
    lq.x = (uint32_t)__bfloat16_as_ushort(l0) | ((uint32_t)__bfloat16_as_ushort(l1) << 16);
    lq.y = (uint32_t)__bfloat16_as_ushort(l2) | ((uint32_t)__bfloat16_as_ushort(l3) << 16);
}

// tiled destination byte offset inside g_a: tile row r (0..127), packed col kp
__device__ __forceinline__ size_t a_off(int bm, int r, int kp) {
    int s = kp >> 6, c = kp & 63;
    return ((size_t)(bm * 48 + s) << 14) + SWZ((uint32_t)(r * 128 + c * 2));
}
// tiled destination byte offset inside g_b: tile row r (0..255), packed col kp
__device__ __forceinline__ size_t b_off(int bn, int r, int kp) {
    int s = kp >> 6, c = kp & 63;
    return ((size_t)(bn * 48 + s) << 15) + SWZ((uint32_t)(r * 128 + c * 2));
}

// ---------------- FUSED conversions (one launch) ----------------
__global__ __launch_bounds__(256) void conv_all_kernel(const float* __restrict__ x,
                                                       const float* __restrict__ W) {
    int bid = blockIdx.x;
    int kq = threadIdx.x << 2;
    if (bid < 32768) {
        int m = bid;
        float4 v = *(const float4*)(x + (size_t)m * DD + kq);
        uint2 hq, lq;
        split4(v, hq, lq);
        int bm = m >> 7, r = m & 127;
        char* base = (char*)g_a;
        *(uint2*)(base + a_off(bm, r, kq)) = hq;
        *(uint2*)(base + a_off(bm, r, 1024 + kq)) = hq;
        *(uint2*)(base + a_off(bm, r, 2048 + kq)) = lq;
    } else if (bid < 36864) {
        int n = bid - 32768;
        float4 v = *(const float4*)(W + (size_t)n * KW + kq);
        uint2 hq, lq;
        split4(v, hq, lq);
        int bn = n >> 8, r = n & 255;
        char* base = (char*)g_b;
        *(uint2*)(base + b_off(bn, r, kq)) = hq;
        *(uint2*)(base + b_off(bn, r, 1024 + kq)) = lq;
        *(uint2*)(base + b_off(bn, r, 2048 + kq)) = hq;
    } else {
        int n = bid - 36864;
        float4 v = *(const float4*)(W + (size_t)n * KW + DD + kq);
        uint2 hq, lq;
        split4(v, hq, lq);
        int gate = n >> 10, j = n & 1023;
        int rp = (j >> 3) * 32 + gate * 8 + (j & 7);
        char* base = (char*)(g_bh + (size_t)rp * KHP2 + kq);
        *(uint2*)(base) = hq;
        *(uint2*)(base + 1024 * 2) = lq;
    }
}

// ---------------- tcgen05 x-GEMM (unchanged from R8) --------
#define GSTG 49152
#define GEMM_SMEM (1024 + 4 * GSTG)  // 197632
__global__ __launch_bounds__(128, 1) void gemm_tc(const float* __restrict__ bias) {
#if HAS_TC5
    extern __shared__ __align__(1024) char smem[];
    uint32_t sbase = smem_u32(smem);
    int tid = threadIdx.x;
    int wid = tid >> 5, lane = tid & 31;
    int bn = blockIdx.x;  // 0..15
    int bm = blockIdx.y;  // 0..255

    if (wid == 0) {
        asm volatile("tcgen05.alloc.cta_group::1.sync.aligned.shared::cta.b32 [%0], %1;"
                     :: "r"(sbase), "r"(256) : "memory");
        asm volatile("tcgen05.relinquish_alloc_permit.cta_group::1.sync.aligned;");
    }
    if (tid == 0) {
#pragma unroll
        for (int i = 0; i < 4; i++) {
            mbar_init(sbase + 8 + i * 8, 1);
            mbar_init(sbase + 40 + i * 8, 1);
        }
        mbar_init(sbase + 72, 1);
    }
    __syncthreads();
    uint32_t tmem;
    asm volatile("ld.shared.b32 %0, [%1];" : "=r"(tmem) : "r"(sbase));

    const char* Asrc = (const char*)g_a + ((size_t)bm * 48 << 14);
    const char* Bsrc = (const char*)g_b + ((size_t)bn * 48 << 15);

    if (tid == 0) {
#pragma unroll
        for (int s = 0; s < 4; s++) {
            uint32_t full = sbase + 8 + s * 8;
            uint32_t dst = sbase + 1024 + s * GSTG;
            mbar_expect_tx(full, GSTG);
            bulk_g2s(dst, Asrc + (size_t)s * 16384, 16384, full);
            bulk_g2s(dst + 16384, Bsrc + (size_t)s * 32768, 32768, full);
        }
        for (int s = 0; s < 48; s++) {
            int b = s & 3;
            uint32_t p = (s >> 2) & 1;
            mbar_wait(sbase + 8 + b * 8, p);
            uint64_t ad = MK_DESC(sbase + 1024 + b * GSTG);
            uint64_t bd = MK_DESC(sbase + 1024 + b * GSTG + 16384);
#pragma unroll
            for (int k = 0; k < 4; k++)
                mma_f16_ss(tmem, ad + k * 2, bd + k * 2, GEMM_IDESC,
                           (s > 0 || k > 0) ? 1u : 0u);
            tc_commit(sbase + 40 + b * 8);
            if (s + 4 < 48) {
                mbar_wait(sbase + 40 + b * 8, p);
                int sn = s + 4;
                uint32_t full = sbase + 8 + b * 8;
                uint32_t dst = sbase + 1024 + b * GSTG;
                mbar_expect_tx(full, GSTG);
                bulk_g2s(dst, Asrc + (size_t)sn * 16384, 16384, full);
                bulk_g2s(dst + 16384, Bsrc + (size_t)sn * 32768, 32768, full);
            }
        }
        tc_commit(sbase + 72);
    }
    mbar_wait(sbase + 72, 0);
    asm volatile("tcgen05.fence::after_thread_sync;" ::: "memory");

    {
        int m = bm * 128 + wid * 32 + lane;
        int s_ = m & 511, b_ = m >> 9;
        float* orow = g_gx + (size_t)(s_ * BB + b_) * G4H + bn * 256;
        const float* brow = bias + bn * 256;
#pragma unroll 1
        for (int cb = 0; cb < 256; cb += 32) {
            uint32_t r[32];
            LDTM_X32(r, tmem + cb);
            asm volatile("tcgen05.wait::ld.sync.aligned;" ::: "memory");
#pragma unroll
            for (int j = 0; j < 32; j += 4) {
                float4 v;
                v.x = __uint_as_float(r[j + 0]) + __ldg(brow + cb + j + 0);
                v.y = __uint_as_float(r[j + 1]) + __ldg(brow + cb + j + 1);
                v.z = __uint_as_float(r[j + 2]) + __ldg(brow + cb + j + 2);
                v.w = __uint_as_float(r[j + 3]) + __ldg(brow + cb + j + 3);
                *(float4*)(orow + cb + j) = v;
            }
        }
    }
    __syncthreads();
    if (wid == 0) {
        asm volatile("tcgen05.dealloc.cta_group::1.sync.aligned.b32 %0, %1;"
                     :: "r"(tmem), "r"(256));
    }
#else
    int tid = threadIdx.x;
    int bn = blockIdx.x, bm = blockIdx.y;
    const char* ab = (const char*)g_a;
    const char* bb = (const char*)g_b;
    for (int idx = tid; idx < 128 * 256; idx += 128) {
        int mi = idx >> 8, ni = idx & 255;
        float acc = 0.f;
        for (int kp = 0; kp < KP; kp++) {
            __nv_bfloat16 av = *(const __nv_bfloat16*)(ab + a_off(bm, mi, kp));
            __nv_bfloat16 bv = *(const __nv_bfloat16*)(bb + b_off(bn, ni, kp));
            acc += __bfloat162float(av) * __bfloat162float(bv);
        }
        int m = bm * 128 + mi, n = bn * 256 + ni;
        int s_ = m & 511, b_ = m >> 9;
        g_gx[(size_t)(s_ * BB + b_) * G4H + n] = acc + bias[n];
    }
#endif
}

// ---------------- grid barrier (atomic, known-good) ----------------
__device__ __forceinline__ void grid_bar() {
    __syncthreads();
    if (threadIdx.x == 0) {
        __threadfence();
        unsigned e = g_epoch;
        unsigned old = atomicAdd(&g_arrive, 1);
        if (old == RNBLK - 1) {
            g_arrive = 0;
            __threadfence();
            atomicExch(&g_epoch, e + 1);
        } else {
            while (*(volatile unsigned*)&g_epoch == e) {}
            __threadfence();
        }
    }
    __syncthreads();
}

// ---------------- persistent tcgen05 recurrent kernel ----------------
// R13 winner + Gx staging moved to warps 4-7, overlapped with the control
// thread's TMA/MMA issue (removes the serial Gx L2 read + one syncthreads).
#define RW_OFF 1024
#define RA_OFF (RW_OFF + 131072)    // 132096, 4 x 16384
#define RGX_OFF (RA_OFF + 65536)    // 197632
#define RLO_OFF (RGX_OFF + 8192)    // 205824
#define RSMEM (RLO_OFF + 8448)      // 214272
__global__ __launch_bounds__(RNTHR, 1) void lstm_tc(float* __restrict__ outp) {
#if HAS_TC5
    extern __shared__ __align__(1024) char smem[];
    uint32_t sbase = smem_u32(smem);
    int tid = threadIdx.x, wid = tid >> 5, lane = tid & 31;
    int cta = blockIdx.x;
    int jb = cta * 8;

    if (wid == 0) {
        asm volatile("tcgen05.alloc.cta_group::1.sync.aligned.shared::cta.b32 [%0], %1;"
                     :: "r"(sbase), "r"(32) : "memory");
        asm volatile("tcgen05.relinquish_alloc_permit.cta_group::1.sync.aligned;");
    }
    if (tid == 0) {
#pragma unroll
        for (int i = 0; i < 4; i++) {
            mbar_init(sbase + 8 + i * 8, 1);
            mbar_init(sbase + 40 + i * 8, 1);
        }
        mbar_init(sbase + 72, 1);
    }
    __syncthreads();
    uint32_t tmem;
    asm volatile("ld.shared.b32 %0, [%1];" : "=r"(tmem) : "r"(sbase));

    // Load resident Wh' slice: 32 chunks x (32 rows x 128B), SW128 swizzled.
    {
        const __nv_bfloat16* wsrc = g_bh + (size_t)cta * 32 * KHP2;
        for (int i = tid; i < 8192; i += RNTHR) {
            int lc = i >> 8, q = i & 255;
            uint4 v = *(const uint4*)(wsrc + (size_t)lc * KHP2 + q * 8);
            int c = q >> 3;
            uint32_t off = (uint32_t)lc * 128 + (q & 7) * 16;
            *(uint4*)(smem + RW_OFF + c * 4096 + SWZ(off)) = v;
        }
    }
    __syncthreads();

    float* gxs = (float*)(smem + RGX_OFF);
    float* loD = (float*)(smem + RLO_OFF);
    float creg[8];
#pragma unroll
    for (int u = 0; u < 8; u++) creg[u] = 0.f;
    int m_ep = wid * 32 + lane;

    int wchunk = jb >> 6;
    uint32_t wc_hi = SWZ((uint32_t)(jb & 63) * 2);

    for (int t = 0; t < SS; t++) {
        // control thread: 4-deep TMA pipeline over 16 chunks (starts immediately)
        if (tid == 0) {
            const char* src = (const char*)g_hA[t & 1];
#pragma unroll
            for (int b = 0; b < 4; b++) {
                uint32_t full = sbase + 8 + b * 8;
                mbar_expect_tx(full, 16384);
                bulk_g2s(sbase + RA_OFF + b * 16384, src + (size_t)b * 16384, 16384, full);
            }
            for (int k = 0; k < 16; k++) {
                int b = k & 3;
                uint32_t par = (k >> 2) & 1;
                mbar_wait(sbase + 8 + b * 8, par);
                uint64_t ad = MK_DESC(sbase + RA_OFF + b * 16384);
                uint64_t bd0 = MK_DESC(sbase + RW_OFF + k * 4096);
                uint64_t bd1 = MK_DESC(sbase + RW_OFF + (k + 16) * 4096);
#pragma unroll
                for (int j = 0; j < 4; j++)
                    mma_f16_ss(tmem, ad + j * 2, bd0 + j * 2, REC_IDESC,
                               (k > 0 || j > 0) ? 1u : 0u);
#pragma unroll
                for (int j = 0; j < 4; j++)
                    mma_f16_ss(tmem, ad + j * 2, bd1 + j * 2, REC_IDESC, 1u);
                tc_commit(sbase + 40 + b * 8);
                if (k + 4 < 16) {
                    mbar_wait(sbase + 40 + b * 8, par);
                    uint32_t full = sbase + 8 + b * 8;
                    mbar_expect_tx(full, 16384);
                    bulk_g2s(sbase + RA_OFF + b * 16384,
                             src + (size_t)(k + 4) * 16384, 16384, full);
                }
            }
            tc_commit(sbase + 72);  // ONE flip per step
        }

        // warps 4-7 stage Gx(t) concurrently with the TMA/MMA issue.
        // Ordered before epilogue reads by the pre-epilogue __syncthreads;
        // ordered after the previous epilogue's reads by grid_bar's syncthreads.
        if (wid >= 4) {
            int idx = (tid - 128) * 2;
#pragma unroll
            for (int r2 = 0; r2 < 2; r2++) {
                int unit = idx + r2;
                int b2 = unit >> 2, gate = unit & 3;
                const float* src = g_gx + (size_t)t * BB * G4H + (size_t)b2 * G4H +
                                   gate * HH + jb;
                float4 v0 = *(const float4*)src;
                float4 v1 = *(const float4*)(src + 4);
                float* dst = gxs + b2 * 32 + gate * 8;
                *(float4*)dst = v0;
                *(float4*)(dst + 4) = v1;
            }
        }

        // all threads: once-per-step wait, parity t&1
        mbar_wait(sbase + 72, t & 1);
        asm volatile("tcgen05.fence::after_thread_sync;" ::: "memory");
        uint32_t rr[32];
        if (wid < 4) {
            LDTM_X32(rr, tmem);
            asm volatile("tcgen05.wait::ld.sync.aligned;" ::: "memory");
        }
        if (wid >= 2 && wid < 4) {
            int m = (wid - 2) * 32 + lane;
            float* lr = loD + m * 33;
#pragma unroll
            for (int j = 0; j < 32; j++) lr[j] = __uint_as_float(rr[j]);
        }
        __syncthreads();
        if (wid < 2) {
            int m = m_ep;
            const float* lr = loD + m * 33;
            float hv[8];
#pragma unroll
            for (int u = 0; u < 8; u++) {
                float gi = __uint_as_float(rr[u]) + lr[u] + gxs[m * 32 + u];
                float gf = __uint_as_float(rr[8 + u]) + lr[8 + u] + gxs[m * 32 + 8 + u];
                float go = __uint_as_float(rr[16 + u]) + lr[16 + u] + gxs[m * 32 + 16 + u];
                float gg = __uint_as_float(rr[24 + u]) + lr[24 + u] + gxs[m * 32 + 24 + u];
                float si = 1.f / (1.f + __expf(-gi));
                float sf = 1.f / (1.f + __expf(-gf));
                float so = 1.f / (1.f + __expf(-go));
                float cn = sf * creg[u] + si * tanhf(gg);
                creg[u] = cn;
                hv[u] = so * tanhf(cn);
            }
            float* op = outp + ((size_t)m * SS + t) * HH + jb;
            float4 o0 = {hv[0], hv[1], hv[2], hv[3]};
            float4 o1 = {hv[4], hv[5], hv[6], hv[7]};
            *(float4*)op = o0;
            *(float4*)(op + 4) = o1;
            uint32_t hp[4], lp[4];
#pragma unroll
            for (int q = 0; q < 4; q++) {
                __nv_bfloat16 b0 = __float2bfloat16(hv[2 * q]);
                __nv_bfloat16 b1 = __float2bfloat16(hv[2 * q + 1]);
                __nv_bfloat16 c0 = __float2bfloat16(hv[2 * q] - __bfloat162float(b0));
                __nv_bfloat16 c1 = __float2bfloat16(hv[2 * q + 1] - __bfloat162float(b1));
                hp[q] = (uint32_t)__bfloat16_as_ushort(b0) |
                        ((uint32_t)__bfloat16_as_ushort(b1) << 16);
                lp[q] = (uint32_t)__bfloat16_as_ushort(c0) |
                        ((uint32_t)__bfloat16_as_ushort(c1) << 16);
            }
            char* img = (char*)g_hA[(t + 1) & 1] + (size_t)wchunk * 16384;
            *(uint4*)(img + (SWZ((uint32_t)m * 128) ^ wc_hi)) = *(uint4*)hp;
            *(uint4*)(img + (SWZ((uint32_t)(m + 64) * 128) ^ wc_hi)) = *(uint4*)lp;
            if (t == SS - 1) {
#pragma unroll
                for (int u = 0; u < 8; u++) {
                    g_hfin[(size_t)m * HH + jb + u] = hv[u];
                    g_cfin[(size_t)m * HH + jb + u] = creg[u];
                }
            }
        }
        grid_bar();
    }
    __syncthreads();
    if (wid == 0) {
        asm volatile("tcgen05.dealloc.cta_group::1.sync.aligned.b32 %0, %1;"
                     :: "r"(tmem), "r"(32));
    }
#else
    // SIMT fallback (never selected at runtime on GB300; correctness-preserving).
    int tid = threadIdx.x;
    int cta = blockIdx.x;
    int jb = cta * 8;
    __shared__ float cs[512];
    __shared__ float hb2[512];
    for (int i = tid; i < 512; i += RNTHR) cs[i] = 0.f;
    __syncthreads();
    for (int t = 0; t < SS; t++) {
        const __nv_bfloat16* hin = g_hsp[t & 1];
        __nv_bfloat16* hout = g_hsp[(t + 1) & 1];
        const float* gxt = g_gx + (size_t)t * BB * G4H;
        for (int e = tid; e < 512; e += RNTHR) {
            int m = e >> 3, u = e & 7;
            float g4[4];
            for (int gate = 0; gate < 4; gate++) {
                const __nv_bfloat16* arow = hin + (size_t)m * KHP2;
                const __nv_bfloat16* brow = g_bh + (size_t)(cta * 32 + gate * 8 + u) * KHP2;
                float acc = 0.f;
                for (int k = 0; k < 1024; k++) {
                    float ahv = __bfloat162float(arow[k]);
                    float alv = __bfloat162float(arow[1024 + k]);
                    float wh = __bfloat162float(brow[k]);
                    float wl = __bfloat162float(brow[1024 + k]);
                    acc += (ahv + alv) * (wh + wl);
                }
                g4[gate] = acc + gxt[(size_t)m * G4H + gate * HH + jb + u];
            }
            float si = 1.f / (1.f + __expf(-g4[0]));
            float sf = 1.f / (1.f + __expf(-g4[1]));
            float so = 1.f / (1.f + __expf(-g4[2]));
            float cn = sf * cs[e] + si * tanhf(g4[3]);
            cs[e] = cn;
            float h = so * tanhf(cn);
            hb2[e] = h;
            outp[((size_t)m * SS + t) * HH + jb + u] = h;
            if (t == SS - 1) {
                g_hfin[(size_t)m * HH + jb + u] = h;
                g_cfin[(size_t)m * HH + jb + u] = cn;
            }
        }
        grid_bar();
        for (int e = tid; e < 512; e += RNTHR) {
            int m = e >> 3, u = e & 7;
            float h = hb2[e];
            __nv_bfloat16 hb = __float2bfloat16(h);
            __nv_bfloat16 lb = __float2bfloat16(h - __bfloat162float(hb));
            hout[(size_t)m * KHP2 + jb + u] = hb;
            hout[(size_t)m * KHP2 + 1024 + jb + u] = lb;
        }
        grid_bar();
    }
#endif
}

// ---------------- tail: final (h, c) leaves if present ----------------
__global__ void tail_kernel(float* __restrict__ dst, int nh, int nc) {
    int i = blockIdx.x * blockDim.x + threadIdx.x;
    if (i < nh) dst[OUT_MAIN + i] = g_hfin[i];
    if (i < nc) dst[OUT_MAIN + 65536 + i] = g_cfin[i];
}

// ---------------- launch ----------------
extern "C" void kernel_launch(void* const* d_in, const int* in_sizes, int n_in,
                              void* d_out, int out_size) {
    const float* x = nullptr;
    const float* W = nullptr;
    const float* bias = nullptr;
    for (int i = 0; i < n_in; i++) {
        if (in_sizes[i] == BB * SS * DD) x = (const float*)d_in[i];
        else if (in_sizes[i] == G4H * KW) W = (const float*)d_in[i];
        else if (in_sizes[i] == G4H) bias = (const float*)d_in[i];
    }
    float* out = (float*)d_out;

    cudaFuncSetAttribute(gemm_tc, cudaFuncAttributeMaxDynamicSharedMemorySize, GEMM_SMEM);
    cudaFuncSetAttribute(lstm_tc, cudaFuncAttributeMaxDynamicSharedMemorySize, RSMEM);

    init_kernel<<<64, 1024>>>();
    conv_all_kernel<<<40960, 256>>>(x, W);

    gemm_tc<<<dim3(16, 256), 128, GEMM_SMEM>>>(bias);

    lstm_tc<<<RNBLK, RNTHR, RSMEM>>>(out);   // 4th launch -> ncu capture window

    if (out_size > OUT_MAIN) {
        int extra = out_size - OUT_MAIN;
        int nh = extra < 65536 ? extra : 65536;
        int nc = extra > 65536 ? (extra - 65536 < 65536 ? extra - 65536 : 65536) : 0;
        tail_kernel<<<64, 1024>>>(out, nh, nc);
    }
}